// round 10
// baseline (speedup 1.0000x reference)
#include <cuda_runtime.h>
#include <cuda_bf16.h>

// loss = sum_{pos} softplus(-p)/n_pos + sum_{neg} softplus(p)/n_neg
// over 8192x8192 f32 + i32. Streaming reduction, LTS-cap-bound (~6.1-6.6 TB/s).
// R10: single kernel, contention-free epilogue.
//   - Each block publishes its partial + sets a PRIVATE flag (1184 distinct
//     addresses -> no atomic convoy, unlike the R3/R5/R8 ticket).
//   - Block 0 polls the flags, then does the fixed-order final reduction.
//   - Grid = exactly one resident wave (148*8) so polling cannot deadlock.
//   - Block 0 resets flags before exit -> graph-replay safe (zero-init start).

#define NBLOCKS  1184        // 148 SMs * 8 CTAs, one full wave
#define NTHREADS 256
#define N_TOTAL  67108864    // 8192*8192
#define N_VEC4   16777216    // N_TOTAL / 4
#define STRIDE   (NBLOCKS * NTHREADS)

__device__ float g_pos[NBLOCKS];
__device__ float g_neg[NBLOCKS];
__device__ int   g_cnt[NBLOCKS];
__device__ int   g_flag[NBLOCKS];   // zero-init; block 0 resets each launch

// softplus(x)  = log1p(e^{-|x|}) + max(x, 0)
// softplus(-x) = log1p(e^{-|x|}) + max(-x, 0)
// -> one EX2 + one LG2 per element regardless of label.
__device__ __forceinline__ void lane_accum(float x, int y,
                                           float& pos, float& neg, int& cnt) {
    float ax     = fabsf(x);
    float common = __logf(1.0f + __expf(-ax));
    bool  ispos  = (y != 0);
    float relu   = fmaxf(ispos ? -x : x, 0.0f);
    float v      = common + relu;
    pos += ispos ? v : 0.0f;
    neg += ispos ? 0.0f : v;
    cnt += ispos ? 1 : 0;
}

__global__ __launch_bounds__(NTHREADS)
void micro_loss_kernel(const float4* __restrict__ pred,
                       const int4*  __restrict__ ty,
                       float* __restrict__ out) {
    float pos = 0.0f, neg = 0.0f;
    int   cnt = 0;

    // Measured-best loop shape (R1): 2 LDG.128 per warp-iteration; chip MLP
    // comes from 64 warps/SM. We sit at the LTS cap — do not touch.
    for (int i = blockIdx.x * NTHREADS + threadIdx.x; i < N_VEC4; i += STRIDE) {
        float4 p = __ldcs(pred + i);   // streaming: touched once
        int4   y = __ldcs(ty + i);
        lane_accum(p.x, y.x, pos, neg, cnt);
        lane_accum(p.y, y.y, pos, neg, cnt);
        lane_accum(p.z, y.z, pos, neg, cnt);
        lane_accum(p.w, y.w, pos, neg, cnt);
    }

    // Block reduction (fixed tree -> deterministic)
    #pragma unroll
    for (int o = 16; o > 0; o >>= 1) {
        pos += __shfl_down_sync(0xFFFFFFFFu, pos, o);
        neg += __shfl_down_sync(0xFFFFFFFFu, neg, o);
        cnt += __shfl_down_sync(0xFFFFFFFFu, cnt, o);
    }
    __shared__ float sp[NTHREADS / 32];
    __shared__ float sn[NTHREADS / 32];
    __shared__ int   sc[NTHREADS / 32];
    int wid = threadIdx.x >> 5;
    int lid = threadIdx.x & 31;
    if (lid == 0) { sp[wid] = pos; sn[wid] = neg; sc[wid] = cnt; }
    __syncthreads();

    if (threadIdx.x == 0) {
        constexpr int NW = NTHREADS / 32;
        float bp = 0.0f, bn = 0.0f; int bc = 0;
        #pragma unroll
        for (int w = 0; w < NW; w++) { bp += sp[w]; bn += sn[w]; bc += sc[w]; }
        g_pos[blockIdx.x] = bp;
        g_neg[blockIdx.x] = bn;
        g_cnt[blockIdx.x] = bc;
        __threadfence();                 // release: partial visible before flag
        *(volatile int*)&g_flag[blockIdx.x] = 1;   // private flag: no contention
    }

    // ---- Block 0: wait for all flags, then final reduction ----
    if (blockIdx.x != 0) return;

    // Each thread polls its strided subset of flags.
    for (int k = threadIdx.x; k < NBLOCKS; k += NTHREADS) {
        while (*(volatile int*)&g_flag[k] == 0) { /* spin; one wave resident */ }
    }
    __syncthreads();
    __threadfence();   // acquire: all partials visible after flags observed

    float fp = 0.0f, fn = 0.0f; int fc = 0;
    for (int k = threadIdx.x; k < NBLOCKS; k += NTHREADS) {
        fp += g_pos[k]; fn += g_neg[k]; fc += g_cnt[k];
        g_flag[k] = 0;                   // reset for next graph replay
    }
    #pragma unroll
    for (int o = 16; o > 0; o >>= 1) {
        fp += __shfl_down_sync(0xFFFFFFFFu, fp, o);
        fn += __shfl_down_sync(0xFFFFFFFFu, fn, o);
        fc += __shfl_down_sync(0xFFFFFFFFu, fc, o);
    }
    if (lid == 0) { sp[wid] = fp; sn[wid] = fn; sc[wid] = fc; }
    __syncthreads();
    if (threadIdx.x == 0) {
        constexpr int NW = NTHREADS / 32;
        float bp = 0.0f, bn = 0.0f; int bc = 0;
        #pragma unroll
        for (int w = 0; w < NW; w++) { bp += sp[w]; bn += sn[w]; bc += sc[w]; }
        float n_pos = (float)bc;
        float n_neg = (float)(N_TOTAL - bc);
        out[0] = bp / n_pos + bn / n_neg;
    }
}

extern "C" void kernel_launch(void* const* d_in, const int* in_sizes, int n_in,
                              void* d_out, int out_size) {
    const float4* pred = (const float4*)d_in[0];  // pred_y: float32 [8192,8192]
    const int4*   ty   = (const int4*)  d_in[1];  // true_y: int32   [8192,8192]
    float*        out  = (float*)d_out;

    micro_loss_kernel<<<NBLOCKS, NTHREADS>>>(pred, ty, out);
}

// round 11
// speedup vs baseline: 1.0208x; 1.0208x over previous
#include <cuda_runtime.h>
#include <cuda_bf16.h>

// loss = sum_{pos} softplus(-p)/n_pos + sum_{neg} softplus(p)/n_neg
// over 8192x8192 f32 + i32. Streaming reduction; main loop sits at the
// structural L2/LTS cap (~6.9 TB/s, ~77us). All remaining time is epilogue.
// R11: hook-style overlap. stage1 triggers PDL completion at kernel START
// (grid = exactly one resident wave, so all CTAs trigger immediately);
// stage2 (256 thr) launches DURING stage1, spin-polls per-block flags
// (data-level sync instead of kernel-boundary sync), and finishes ~1us
// after the last block publishes. Avoids both the in-kernel join tail
// (fused variants: +10us) and the serialized teardown+launch (split: +5.5us).

#define NBLOCKS  1184        // 148 SMs * 8 CTAs = exactly one wave
#define NTHREADS 256
#define N_TOTAL  67108864    // 8192*8192
#define N_VEC4   16777216    // N_TOTAL / 4

__device__ float g_pos[NBLOCKS];
__device__ float g_neg[NBLOCKS];
__device__ int   g_cnt[NBLOCKS];
__device__ int   g_flag[NBLOCKS];   // zero-init; stage2 resets after consuming

// softplus(x)  = log1p(e^{-|x|}) + max(x, 0)
// softplus(-x) = log1p(e^{-|x|}) + max(-x, 0)
// -> one EX2 + one LG2 per element regardless of label.
__device__ __forceinline__ void lane_accum(float x, int y,
                                           float& pos, float& neg, int& cnt) {
    float ax     = fabsf(x);
    float common = __logf(1.0f + __expf(-ax));
    bool  ispos  = (y != 0);
    float relu   = fmaxf(ispos ? -x : x, 0.0f);
    float v      = common + relu;
    pos += ispos ? v : 0.0f;
    neg += ispos ? 0.0f : v;
    cnt += ispos ? 1 : 0;
}

__global__ __launch_bounds__(NTHREADS)
void reduce_stage1(const float4* __restrict__ pred,
                   const int4*  __restrict__ ty) {
    // Fire the PDL event immediately: the whole grid is resident at T=0
    // (one full wave), so stage2 becomes launchable while we stream.
    cudaTriggerProgrammaticLaunchCompletion();

    float pos = 0.0f, neg = 0.0f;
    int   cnt = 0;

    // Measured-best loop shape (R1/R9): 2 LDG.128 per warp-iteration,
    // runtime stride, chip MLP from 64 warps/SM. Do not touch.
    const int stride = gridDim.x * blockDim.x;
    for (int i = blockIdx.x * blockDim.x + threadIdx.x; i < N_VEC4; i += stride) {
        float4 p = __ldcs(pred + i);   // streaming: touched once
        int4   y = __ldcs(ty + i);
        lane_accum(p.x, y.x, pos, neg, cnt);
        lane_accum(p.y, y.y, pos, neg, cnt);
        lane_accum(p.z, y.z, pos, neg, cnt);
        lane_accum(p.w, y.w, pos, neg, cnt);
    }

    // Block reduction (fixed tree -> deterministic)
    #pragma unroll
    for (int o = 16; o > 0; o >>= 1) {
        pos += __shfl_down_sync(0xFFFFFFFFu, pos, o);
        neg += __shfl_down_sync(0xFFFFFFFFu, neg, o);
        cnt += __shfl_down_sync(0xFFFFFFFFu, cnt, o);
    }
    __shared__ float sp[NTHREADS / 32];
    __shared__ float sn[NTHREADS / 32];
    __shared__ int   sc[NTHREADS / 32];
    int wid = threadIdx.x >> 5;
    int lid = threadIdx.x & 31;
    if (lid == 0) { sp[wid] = pos; sn[wid] = neg; sc[wid] = cnt; }
    __syncthreads();

    if (threadIdx.x == 0) {
        constexpr int NW = NTHREADS / 32;
        float bp = 0.0f, bn = 0.0f; int bc = 0;
        #pragma unroll
        for (int w = 0; w < NW; w++) { bp += sp[w]; bn += sn[w]; bc += sc[w]; }
        g_pos[blockIdx.x] = bp;
        g_neg[blockIdx.x] = bn;
        g_cnt[blockIdx.x] = bc;
        __threadfence();                              // release partials
        *(volatile int*)&g_flag[blockIdx.x] = 1;      // private flag
    }
}

__global__ __launch_bounds__(NTHREADS)
void reduce_stage2(float* __restrict__ out) {
    // Data-level sync: wait for every block's flag (NOT grid completion).
    for (int k = threadIdx.x; k < NBLOCKS; k += NTHREADS) {
        while (*(volatile int*)&g_flag[k] == 0) { }
    }
    __syncthreads();
    __threadfence();   // acquire: all partials visible

    float fp = 0.0f, fn = 0.0f; int fc = 0;
    for (int k = threadIdx.x; k < NBLOCKS; k += NTHREADS) {
        fp += g_pos[k]; fn += g_neg[k]; fc += g_cnt[k];
        g_flag[k] = 0;                 // reset for next graph replay
    }
    #pragma unroll
    for (int o = 16; o > 0; o >>= 1) {
        fp += __shfl_down_sync(0xFFFFFFFFu, fp, o);
        fn += __shfl_down_sync(0xFFFFFFFFu, fn, o);
        fc += __shfl_down_sync(0xFFFFFFFFu, fc, o);
    }
    __shared__ float sp[NTHREADS / 32];
    __shared__ float sn[NTHREADS / 32];
    __shared__ int   sc[NTHREADS / 32];
    int wid = threadIdx.x >> 5;
    int lid = threadIdx.x & 31;
    if (lid == 0) { sp[wid] = fp; sn[wid] = fn; sc[wid] = fc; }
    __syncthreads();
    if (threadIdx.x == 0) {
        constexpr int NW = NTHREADS / 32;
        float bp = 0.0f, bn = 0.0f; int bc = 0;
        #pragma unroll
        for (int w = 0; w < NW; w++) { bp += sp[w]; bn += sn[w]; bc += sc[w]; }
        float n_pos = (float)bc;
        float n_neg = (float)(N_TOTAL - bc);
        out[0] = bp / n_pos + bn / n_neg;
    }
}

extern "C" void kernel_launch(void* const* d_in, const int* in_sizes, int n_in,
                              void* d_out, int out_size) {
    const float4* pred = (const float4*)d_in[0];  // pred_y: float32 [8192,8192]
    const int4*   ty   = (const int4*)  d_in[1];  // true_y: int32   [8192,8192]
    float*        out  = (float*)d_out;

    reduce_stage1<<<NBLOCKS, NTHREADS>>>(pred, ty);

    // Launch stage2 with PDL so it becomes resident DURING stage1 and syncs
    // on the flags, not the kernel boundary.
    cudaLaunchConfig_t cfg = {};
    cfg.gridDim  = dim3(1, 1, 1);
    cfg.blockDim = dim3(NTHREADS, 1, 1);
    cfg.dynamicSmemBytes = 0;
    cfg.stream = 0;
    cudaLaunchAttribute attr;
    attr.id = cudaLaunchAttributeProgrammaticStreamSerialization;
    attr.val.programmaticStreamSerializationAllowed = 1;
    cfg.attrs = &attr;
    cfg.numAttrs = 1;

    cudaError_t err = cudaLaunchKernelEx(&cfg, reduce_stage2, out);
    if (err != cudaSuccess) {
        (void)cudaGetLastError();          // clear sticky error
        // Plain fallback: runs after stage1 completes; flags already set,
        // poll exits immediately. Correct either way.
        reduce_stage2<<<1, NTHREADS>>>(out);
    }
}

// round 12
// speedup vs baseline: 1.0220x; 1.0011x over previous
#include <cuda_runtime.h>
#include <cuda_bf16.h>

// loss = sum_{pos} softplus(-p)/n_pos + sum_{neg} softplus(p)/n_neg
// over 8192x8192 f32 + i32. Streaming reduction; main loop sits at the
// structural L2/LTS cap (~6.9 TB/s, ~77us). All remaining time is epilogue.
// R11: hook-style overlap. stage1 triggers PDL completion at kernel START
// (grid = exactly one resident wave, so all CTAs trigger immediately);
// stage2 (256 thr) launches DURING stage1, spin-polls per-block flags
// (data-level sync instead of kernel-boundary sync), and finishes ~1us
// after the last block publishes. Avoids both the in-kernel join tail
// (fused variants: +10us) and the serialized teardown+launch (split: +5.5us).

#define NBLOCKS  1184        // 148 SMs * 8 CTAs = exactly one wave
#define NTHREADS 256
#define N_TOTAL  67108864    // 8192*8192
#define N_VEC4   16777216    // N_TOTAL / 4

__device__ float g_pos[NBLOCKS];
__device__ float g_neg[NBLOCKS];
__device__ int   g_cnt[NBLOCKS];
__device__ int   g_flag[NBLOCKS];   // zero-init; stage2 resets after consuming

// softplus(x)  = log1p(e^{-|x|}) + max(x, 0)
// softplus(-x) = log1p(e^{-|x|}) + max(-x, 0)
// -> one EX2 + one LG2 per element regardless of label.
__device__ __forceinline__ void lane_accum(float x, int y,
                                           float& pos, float& neg, int& cnt) {
    float ax     = fabsf(x);
    float common = __logf(1.0f + __expf(-ax));
    bool  ispos  = (y != 0);
    float relu   = fmaxf(ispos ? -x : x, 0.0f);
    float v      = common + relu;
    pos += ispos ? v : 0.0f;
    neg += ispos ? 0.0f : v;
    cnt += ispos ? 1 : 0;
}

__global__ __launch_bounds__(NTHREADS)
void reduce_stage1(const float4* __restrict__ pred,
                   const int4*  __restrict__ ty) {
    // Fire the PDL event immediately: the whole grid is resident at T=0
    // (one full wave), so stage2 becomes launchable while we stream.
    cudaTriggerProgrammaticLaunchCompletion();

    float pos = 0.0f, neg = 0.0f;
    int   cnt = 0;

    // Measured-best loop shape (R1/R9): 2 LDG.128 per warp-iteration,
    // runtime stride, chip MLP from 64 warps/SM. Do not touch.
    const int stride = gridDim.x * blockDim.x;
    for (int i = blockIdx.x * blockDim.x + threadIdx.x; i < N_VEC4; i += stride) {
        float4 p = __ldcs(pred + i);   // streaming: touched once
        int4   y = __ldcs(ty + i);
        lane_accum(p.x, y.x, pos, neg, cnt);
        lane_accum(p.y, y.y, pos, neg, cnt);
        lane_accum(p.z, y.z, pos, neg, cnt);
        lane_accum(p.w, y.w, pos, neg, cnt);
    }

    // Block reduction (fixed tree -> deterministic)
    #pragma unroll
    for (int o = 16; o > 0; o >>= 1) {
        pos += __shfl_down_sync(0xFFFFFFFFu, pos, o);
        neg += __shfl_down_sync(0xFFFFFFFFu, neg, o);
        cnt += __shfl_down_sync(0xFFFFFFFFu, cnt, o);
    }
    __shared__ float sp[NTHREADS / 32];
    __shared__ float sn[NTHREADS / 32];
    __shared__ int   sc[NTHREADS / 32];
    int wid = threadIdx.x >> 5;
    int lid = threadIdx.x & 31;
    if (lid == 0) { sp[wid] = pos; sn[wid] = neg; sc[wid] = cnt; }
    __syncthreads();

    if (threadIdx.x == 0) {
        constexpr int NW = NTHREADS / 32;
        float bp = 0.0f, bn = 0.0f; int bc = 0;
        #pragma unroll
        for (int w = 0; w < NW; w++) { bp += sp[w]; bn += sn[w]; bc += sc[w]; }
        g_pos[blockIdx.x] = bp;
        g_neg[blockIdx.x] = bn;
        g_cnt[blockIdx.x] = bc;
        __threadfence();                              // release partials
        *(volatile int*)&g_flag[blockIdx.x] = 1;      // private flag
    }
}

__global__ __launch_bounds__(NTHREADS)
void reduce_stage2(float* __restrict__ out) {
    // Data-level sync: wait for every block's flag (NOT grid completion).
    for (int k = threadIdx.x; k < NBLOCKS; k += NTHREADS) {
        while (*(volatile int*)&g_flag[k] == 0) { }
    }
    __syncthreads();
    __threadfence();   // acquire: all partials visible

    float fp = 0.0f, fn = 0.0f; int fc = 0;
    for (int k = threadIdx.x; k < NBLOCKS; k += NTHREADS) {
        fp += g_pos[k]; fn += g_neg[k]; fc += g_cnt[k];
        g_flag[k] = 0;                 // reset for next graph replay
    }
    #pragma unroll
    for (int o = 16; o > 0; o >>= 1) {
        fp += __shfl_down_sync(0xFFFFFFFFu, fp, o);
        fn += __shfl_down_sync(0xFFFFFFFFu, fn, o);
        fc += __shfl_down_sync(0xFFFFFFFFu, fc, o);
    }
    __shared__ float sp[NTHREADS / 32];
    __shared__ float sn[NTHREADS / 32];
    __shared__ int   sc[NTHREADS / 32];
    int wid = threadIdx.x >> 5;
    int lid = threadIdx.x & 31;
    if (lid == 0) { sp[wid] = fp; sn[wid] = fn; sc[wid] = fc; }
    __syncthreads();
    if (threadIdx.x == 0) {
        constexpr int NW = NTHREADS / 32;
        float bp = 0.0f, bn = 0.0f; int bc = 0;
        #pragma unroll
        for (int w = 0; w < NW; w++) { bp += sp[w]; bn += sn[w]; bc += sc[w]; }
        float n_pos = (float)bc;
        float n_neg = (float)(N_TOTAL - bc);
        out[0] = bp / n_pos + bn / n_neg;
    }
}

extern "C" void kernel_launch(void* const* d_in, const int* in_sizes, int n_in,
                              void* d_out, int out_size) {
    const float4* pred = (const float4*)d_in[0];  // pred_y: float32 [8192,8192]
    const int4*   ty   = (const int4*)  d_in[1];  // true_y: int32   [8192,8192]
    float*        out  = (float*)d_out;

    reduce_stage1<<<NBLOCKS, NTHREADS>>>(pred, ty);

    // Launch stage2 with PDL so it becomes resident DURING stage1 and syncs
    // on the flags, not the kernel boundary.
    cudaLaunchConfig_t cfg = {};
    cfg.gridDim  = dim3(1, 1, 1);
    cfg.blockDim = dim3(NTHREADS, 1, 1);
    cfg.dynamicSmemBytes = 0;
    cfg.stream = 0;
    cudaLaunchAttribute attr;
    attr.id = cudaLaunchAttributeProgrammaticStreamSerialization;
    attr.val.programmaticStreamSerializationAllowed = 1;
    cfg.attrs = &attr;
    cfg.numAttrs = 1;

    cudaError_t err = cudaLaunchKernelEx(&cfg, reduce_stage2, out);
    if (err != cudaSuccess) {
        (void)cudaGetLastError();          // clear sticky error
        // Plain fallback: runs after stage1 completes; flags already set,
        // poll exits immediately. Correct either way.
        reduce_stage2<<<1, NTHREADS>>>(out);
    }
}